// round 15
// baseline (speedup 1.0000x reference)
#include <cuda_runtime.h>
#include <cuda_fp16.h>
#include <mma.h>
#include <cstdint>

#define NN 16384
#define DF 256
#define MT 128          // rows per CTA
#define BK 64           // K chunk
#define NCH (NN / BK)   // 256 chunks

// smem map (bytes)
#define SM_DEG  0                        // 128 ints (512 B)
#define SM_BIAS 512                      // 256 floats (1024 B)
#define SM_A    1536                     // 2 x (128 x 72 halves) = 36864 B
#define ABUF_B  18432
#define SM_B    (1536 + 36864)           // 2 x (64 x 264 halves) = 67584 B
#define BBUF_B  33792
#define ASTR    72                       // A row stride (halves)
#define BSTR    264                      // B row stride (halves)
#define SMEM_TOTAL (SM_B + 2 * BBUF_B)   // 105984

__device__ __half g_xh[(size_t)NN * DF];    // x fp16 row-major
__device__ __half g_Wh[DF * DF];            // W fp16 row-major [out][in]

// ---------------- prep kernels ----------------
__global__ void k_convX(const float* __restrict__ x) {
    const size_t i = (size_t)blockIdx.x * 256 + threadIdx.x;   // one float4 each
    const float4 v = ((const float4*)x)[i];
    __half2* d = (__half2*)(g_xh + i * 4);
    d[0] = __floats2half2_rn(v.x, v.y);
    d[1] = __floats2half2_rn(v.z, v.w);
}
__global__ void k_convW(const float* __restrict__ W) {
    const int i = blockIdx.x * 256 + threadIdx.x;
    g_Wh[i] = __float2half(W[i]);
}

// ---------------- fused main: out = ((A_tile @ x)/deg) @ W^T + b ----------------
__global__ void __launch_bounds__(256)
k_main(const int* __restrict__ adj, const float* __restrict__ bias,
       float* __restrict__ out) {
    using namespace nvcuda;
    extern __shared__ char smem[];
    int* degs = (int*)(smem + SM_DEG);
    float* biasS = (float*)(smem + SM_BIAS);

    const int tid = threadIdx.x;
    const int w = tid >> 5, lid = tid & 31;
    const int blk = blockIdx.x;

    if (tid < 128) degs[tid] = 0;
    biasS[tid] = bias[tid];
    biasS[tid + 256 - 256] = biasS[tid];           // keep simple; 256 threads cover 256
    // (256 threads, one each)

    // A loader: 8 int4/thread/chunk: rows ar0+16i (i<8), int4-col ac4
    const int ar0 = tid >> 4, ac4 = tid & 15;
    const int4* arow[8];
#pragma unroll
    for (int i = 0; i < 8; ++i)
        arow[i] = (const int4*)(adj + (size_t)(blk * MT + ar0 + 16 * i) * NN) + ac4;
    int degl[8];
#pragma unroll
    for (int i = 0; i < 8; ++i) degl[i] = 0;

    // B loader: 8 x 16B/thread/chunk: k-rows br0+8i, feat-col bc*8
    const int br0 = tid >> 5, bc = tid & 31;

    // warp tile: 64 rows x 64 cols (wm in {0,1}, wn in {0..3})
    const int wm = w >> 2, wn = w & 3;

    wmma::fragment<wmma::accumulator, 16, 16, 16, float> acc[4][4];
#pragma unroll
    for (int tm = 0; tm < 4; ++tm)
#pragma unroll
        for (int tn = 0; tn < 4; ++tn) wmma::fill_fragment(acc[tm][tn], 0.0f);

    const uint32_t ab0 = (uint32_t)__cvta_generic_to_shared(smem + SM_A);
    const uint32_t bb0 = (uint32_t)__cvta_generic_to_shared(smem + SM_B);

    // ---- prologue: B[0] cp.async, A[0] LDG -> convert -> smem buf0 ----
#pragma unroll
    for (int i = 0; i < 8; ++i) {
        const int row = br0 + 8 * i;
        const __half* src = g_xh + (size_t)row * DF + bc * 8;
        asm volatile("cp.async.cg.shared.global [%0], [%1], 16;"
                     :: "r"(bb0 + row * (BSTR * 2) + bc * 16), "l"(src) : "memory");
    }
    asm volatile("cp.async.commit_group;" ::: "memory");
#pragma unroll
    for (int i = 0; i < 8; ++i) {
        const int4 v = arow[i][0];
        degl[i] += v.x + v.y + v.z + v.w;
        const uint32_t u0 = (uint32_t)v.x * 0x3C00u + (uint32_t)v.y * 0x3C000000u;
        const uint32_t u1 = (uint32_t)v.z * 0x3C00u + (uint32_t)v.w * 0x3C000000u;
        asm volatile("st.shared.v2.b32 [%0], {%1, %2};"
                     :: "r"(ab0 + (ar0 + 16 * i) * (ASTR * 2) + ac4 * 8),
                        "r"(u0), "r"(u1));
    }

    for (int c = 0; c < NCH; ++c) {
        asm volatile("cp.async.wait_group 0;" ::: "memory");
        __syncthreads();

        // prefetch chunk c+1: B via cp.async, A into regs (stored after compute)
        int4 av[8];
        if (c + 1 < NCH) {
            const int k0n = (c + 1) * BK;
            const uint32_t bb = bb0 + ((c + 1) & 1) * BBUF_B;
#pragma unroll
            for (int i = 0; i < 8; ++i) {
                const int row = br0 + 8 * i;
                const __half* src = g_xh + (size_t)(k0n + row) * DF + bc * 8;
                asm volatile("cp.async.cg.shared.global [%0], [%1], 16;"
                             :: "r"(bb + row * (BSTR * 2) + bc * 16), "l"(src) : "memory");
            }
#pragma unroll
            for (int i = 0; i < 8; ++i) av[i] = arow[i][(c + 1) * 16];
        }
        asm volatile("cp.async.commit_group;" ::: "memory");

        // compute chunk c: acc += A(64x64) @ B(64x64)
        const __half* As = (const __half*)(smem + SM_A) + (c & 1) * (ABUF_B / 2);
        const __half* Bs = (const __half*)(smem + SM_B) + (c & 1) * (BBUF_B / 2);
#pragma unroll
        for (int kk = 0; kk < 4; ++kk) {
            wmma::fragment<wmma::matrix_a, 16, 16, 16, half, wmma::row_major> a[4];
#pragma unroll
            for (int tm = 0; tm < 4; ++tm)
                wmma::load_matrix_sync(a[tm], As + (wm * 64 + tm * 16) * ASTR + kk * 16, ASTR);
#pragma unroll
            for (int tn = 0; tn < 4; ++tn) {
                wmma::fragment<wmma::matrix_b, 16, 16, 16, half, wmma::row_major> b;
                wmma::load_matrix_sync(b, Bs + (kk * 16) * BSTR + wn * 64 + tn * 16, BSTR);
#pragma unroll
                for (int tm = 0; tm < 4; ++tm)
                    wmma::mma_sync(acc[tm][tn], a[tm], b, acc[tm][tn]);
            }
        }

        // store A[c+1] (convert + degree) into the other A buffer
        if (c + 1 < NCH) {
            const uint32_t ab = ab0 + ((c + 1) & 1) * ABUF_B;
#pragma unroll
            for (int i = 0; i < 8; ++i) {
                const int4 v = av[i];
                degl[i] += v.x + v.y + v.z + v.w;
                const uint32_t u0 = (uint32_t)v.x * 0x3C00u + (uint32_t)v.y * 0x3C000000u;
                const uint32_t u1 = (uint32_t)v.z * 0x3C00u + (uint32_t)v.w * 0x3C000000u;
                asm volatile("st.shared.v2.b32 [%0], {%1, %2};"
                             :: "r"(ab + (ar0 + 16 * i) * (ASTR * 2) + ac4 * 8),
                                "r"(u0), "r"(u1));
            }
        }
        __syncthreads();
    }

    // degree reduction
#pragma unroll
    for (int i = 0; i < 8; ++i) atomicAdd(&degs[ar0 + 16 * i], degl[i]);
    __syncthreads();

    // ---- epilogue 1: scale by 1/deg, fp16 agg -> smem (reuse B region) ----
    __half* aggS = (__half*)(smem + SM_B);              // 128 x 256, stride BSTR
    float* scratch = (float*)(smem + SM_A) + w * 256;   // 16x16 per warp
#pragma unroll
    for (int tm = 0; tm < 4; ++tm) {
#pragma unroll
        for (int tn = 0; tn < 4; ++tn) {
            wmma::store_matrix_sync(scratch, acc[tm][tn], 16, wmma::mem_row_major);
            __syncwarp();
            const int r = lid >> 1, c0 = (lid & 1) * 8;
            const int lrow = wm * 64 + tm * 16 + r;
            const float inv = 1.0f / (float)degs[lrow];
            const float* s = scratch + r * 16 + c0;
            uint32_t pk[4];
#pragma unroll
            for (int j = 0; j < 4; ++j) {
                __half2 h = __floats2half2_rn(s[2 * j] * inv, s[2 * j + 1] * inv);
                pk[j] = *reinterpret_cast<uint32_t*>(&h);
            }
            *(uint4*)(aggS + (size_t)lrow * BSTR + wn * 64 + tn * 16 + c0) =
                make_uint4(pk[0], pk[1], pk[2], pk[3]);
            __syncwarp();
        }
    }
    __syncthreads();

    // ---- stage 2: out_tile = aggS @ W^T + b (W streamed from L2) ----
    wmma::fragment<wmma::accumulator, 16, 16, 16, float> acc2[4][4];
#pragma unroll
    for (int tm = 0; tm < 4; ++tm)
#pragma unroll
        for (int tn = 0; tn < 4; ++tn) wmma::fill_fragment(acc2[tm][tn], 0.0f);

#pragma unroll 4
    for (int k16 = 0; k16 < 16; ++k16) {
        wmma::fragment<wmma::matrix_a, 16, 16, 16, half, wmma::row_major> a[4];
#pragma unroll
        for (int tm = 0; tm < 4; ++tm)
            wmma::load_matrix_sync(a[tm], aggS + (wm * 64 + tm * 16) * BSTR + k16 * 16, BSTR);
#pragma unroll
        for (int tn = 0; tn < 4; ++tn) {
            wmma::fragment<wmma::matrix_b, 16, 16, 16, half, wmma::col_major> b;
            wmma::load_matrix_sync(b, g_Wh + (size_t)(wn * 64 + tn * 16) * DF + k16 * 16, DF);
#pragma unroll
            for (int tm = 0; tm < 4; ++tm)
                wmma::mma_sync(acc2[tm][tn], a[tm], b, acc2[tm][tn]);
        }
    }

    // ---- epilogue 2: + bias, store f32 coalesced ----
#pragma unroll
    for (int tm = 0; tm < 4; ++tm) {
#pragma unroll
        for (int tn = 0; tn < 4; ++tn) {
            wmma::store_matrix_sync(scratch, acc2[tm][tn], 16, wmma::mem_row_major);
            __syncwarp();
            const int r = lid >> 1, c0 = (lid & 1) * 8;
            const int grow = blk * MT + wm * 64 + tm * 16 + r;
            const int gcol = wn * 64 + tn * 16 + c0;
            const float* s = scratch + r * 16 + c0;
            float4 o0, o1;
            o0.x = s[0] + biasS[gcol + 0];  o0.y = s[1] + biasS[gcol + 1];
            o0.z = s[2] + biasS[gcol + 2];  o0.w = s[3] + biasS[gcol + 3];
            o1.x = s[4] + biasS[gcol + 4];  o1.y = s[5] + biasS[gcol + 5];
            o1.z = s[6] + biasS[gcol + 6];  o1.w = s[7] + biasS[gcol + 7];
            float4* dst = (float4*)(out + (size_t)grow * DF + gcol);
            dst[0] = o0;
            dst[1] = o1;
            __syncwarp();
        }
    }
}

extern "C" void kernel_launch(void* const* d_in, const int* in_sizes, int n_in,
                              void* d_out, int out_size) {
    const float* x    = (const float*)d_in[0];
    const int*   adj  = (const int*)d_in[1];
    const float* W    = (const float*)d_in[2];
    const float* bias = (const float*)d_in[3];
    float* out = (float*)d_out;

    cudaFuncSetAttribute((const void*)k_main,
                         cudaFuncAttributeMaxDynamicSharedMemorySize, SMEM_TOTAL);

    k_convX<<<(NN * DF / 4) / 256, 256>>>(x);
    k_convW<<<DF * DF / 256, 256>>>(W);
    k_main<<<NN / MT, 256, SMEM_TOTAL>>>(adj, bias, out);
}

// round 16
// speedup vs baseline: 1.0699x; 1.0699x over previous
#include <cuda_runtime.h>
#include <cuda_fp16.h>
#include <mma.h>
#include <cstdint>

#define NN 16384
#define DF 256
#define MT 128          // rows per CTA
#define BK 64           // K chunk
#define NCH (NN / BK)   // 256 chunks

// smem map (bytes)
#define SM_DEG  0                        // 128 ints (512 B)
#define SM_BIAS 512                      // 256 floats (1024 B)
#define SM_A    1536                     // 2 x (128 x 72 halves) = 36864 B
#define ABUF_B  18432
#define SM_B    (1536 + 36864)           // 2 x (64 x 264 halves) = 67584 B
#define BBUF_B  33792
#define ASTR    72                       // A row stride (halves)
#define BSTR    264                      // B row stride (halves)
#define SMEM_TOTAL (SM_B + 2 * BBUF_B)   // 105984

__device__ __half g_xh[(size_t)NN * DF];    // x fp16 row-major
__device__ __half g_Wh[DF * DF];            // W fp16 row-major [out][in]

// ---------------- merged prep: x -> fp16, W -> fp16 ----------------
#define XBLKS 4096      // 4096 blocks x 256 threads x 1 float4 = NN*DF floats
__global__ void k_prep(const float* __restrict__ x, const float* __restrict__ W) {
    if (blockIdx.x < XBLKS) {
        const size_t i = (size_t)blockIdx.x * 256 + threadIdx.x;
        const float4 v = ((const float4*)x)[i];
        __half2* d = (__half2*)(g_xh + i * 4);
        d[0] = __floats2half2_rn(v.x, v.y);
        d[1] = __floats2half2_rn(v.z, v.w);
    } else {
        const int i = (blockIdx.x - XBLKS) * 256 + threadIdx.x;
        g_Wh[i] = __float2half(W[i]);
    }
}

// ---------------- fused main: out = ((A_tile @ x)/deg) @ W^T + b ----------------
__global__ void __launch_bounds__(512)
k_main(const int* __restrict__ adj, const float* __restrict__ bias,
       float* __restrict__ out) {
    using namespace nvcuda;
    extern __shared__ char smem[];
    int* degs = (int*)(smem + SM_DEG);
    float* biasS = (float*)(smem + SM_BIAS);

    const int tid = threadIdx.x;
    const int w = tid >> 5, lid = tid & 31;
    const int blk = blockIdx.x;

    if (tid < 128) degs[tid] = 0;
    if (tid < 256) biasS[tid] = bias[tid];

    // A loader mapping: per chunk, thread handles 4 int4 (rows r0+32i, int4-col c4)
    const int r0 = tid >> 4, c4 = tid & 15;
    const int4* arow[4];
    int degl[4] = {0, 0, 0, 0};
#pragma unroll
    for (int i = 0; i < 4; ++i)
        arow[i] = (const int4*)(adj + (size_t)(blk * MT + r0 + 32 * i) * NN) + c4;

    // B loader mapping: 4 x 16B per chunk (k-rows brow0+16i, feat-col bcol*8)
    const int brow0 = tid >> 5, bcol = tid & 31;

    // warp tile: 32 rows x 64 cols  (wm in {0..3}, wn in {0..3})
    const int wm = w >> 2, wn = w & 3;

    wmma::fragment<wmma::accumulator, 16, 16, 16, float> acc[2][4];
#pragma unroll
    for (int tm = 0; tm < 2; ++tm)
#pragma unroll
        for (int tn = 0; tn < 4; ++tn) wmma::fill_fragment(acc[tm][tn], 0.0f);

    const uint32_t ab0 = (uint32_t)__cvta_generic_to_shared(smem + SM_A);
    const uint32_t bb0 = (uint32_t)__cvta_generic_to_shared(smem + SM_B);

    // prologue: B[0] cp.async, A[0] -> regs
#pragma unroll
    for (int i = 0; i < 4; ++i) {
        const int row = brow0 + 16 * i;
        const __half* src = g_xh + (size_t)row * DF + bcol * 8;
        asm volatile("cp.async.cg.shared.global [%0], [%1], 16;"
                     :: "r"(bb0 + row * (BSTR * 2) + bcol * 16), "l"(src) : "memory");
    }
    asm volatile("cp.async.commit_group;" ::: "memory");
    int4 av[4];
#pragma unroll
    for (int i = 0; i < 4; ++i) av[i] = arow[i][0];

    for (int c = 0; c < NCH; ++c) {
        // 1) store A[c] (regs -> Abuf[c&1]), fused degree accumulation
        const uint32_t ab = ab0 + (c & 1) * ABUF_B;
#pragma unroll
        for (int i = 0; i < 4; ++i) {
            const int4 v = av[i];
            degl[i] += v.x + v.y + v.z + v.w;
            const uint32_t u0 = (uint32_t)v.x * 0x3C00u + (uint32_t)v.y * 0x3C000000u;
            const uint32_t u1 = (uint32_t)v.z * 0x3C00u + (uint32_t)v.w * 0x3C000000u;
            asm volatile("st.shared.v2.b32 [%0], {%1, %2};"
                         :: "r"(ab + (r0 + 32 * i) * (ASTR * 2) + c4 * 8),
                            "r"(u0), "r"(u1));
        }
        // 2) B[c] landed
        asm volatile("cp.async.wait_group 0;" ::: "memory");
        // 3) single barrier: A[c] stores visible, all warps past compute c-1
        __syncthreads();

        // 4) prefetch chunk c+1: B cp.async into Bbuf[(c+1)&1], A -> regs
        if (c + 1 < NCH) {
            const int k0n = (c + 1) * BK;
            const uint32_t bb = bb0 + ((c + 1) & 1) * BBUF_B;
#pragma unroll
            for (int i = 0; i < 4; ++i) {
                const int row = brow0 + 16 * i;
                const __half* src = g_xh + (size_t)(k0n + row) * DF + bcol * 8;
                asm volatile("cp.async.cg.shared.global [%0], [%1], 16;"
                             :: "r"(bb + row * (BSTR * 2) + bcol * 16), "l"(src)
                             : "memory");
            }
            asm volatile("cp.async.commit_group;" ::: "memory");
#pragma unroll
            for (int i = 0; i < 4; ++i) av[i] = arow[i][(c + 1) * 16];
        }

        // 5) compute chunk c: acc += A(32x64) @ B(64x64)
        const __half* As = (const __half*)(smem + SM_A) + (c & 1) * (ABUF_B / 2);
        const __half* Bs = (const __half*)(smem + SM_B) + (c & 1) * (BBUF_B / 2);
#pragma unroll
        for (int kk = 0; kk < 4; ++kk) {
            wmma::fragment<wmma::matrix_a, 16, 16, 16, half, wmma::row_major> a0, a1;
            wmma::load_matrix_sync(a0, As + (wm * 32 + 0) * ASTR + kk * 16, ASTR);
            wmma::load_matrix_sync(a1, As + (wm * 32 + 16) * ASTR + kk * 16, ASTR);
#pragma unroll
            for (int tn = 0; tn < 4; ++tn) {
                wmma::fragment<wmma::matrix_b, 16, 16, 16, half, wmma::row_major> b;
                wmma::load_matrix_sync(b, Bs + (kk * 16) * BSTR + wn * 64 + tn * 16, BSTR);
                wmma::mma_sync(acc[0][tn], a0, b, acc[0][tn]);
                wmma::mma_sync(acc[1][tn], a1, b, acc[1][tn]);
            }
        }
        // no trailing barrier — next iteration's barrier provides the ordering
    }

    // degree reduction
    __syncthreads();
#pragma unroll
    for (int i = 0; i < 4; ++i) atomicAdd(&degs[r0 + 32 * i], degl[i]);
    __syncthreads();

    // ---- epilogue 1: scale by 1/deg, write fp16 agg into smem (reuse B region) ----
    __half* aggS = (__half*)(smem + SM_B);              // 128 x 256, stride BSTR
    float* scratch = (float*)(smem + SM_A) + w * 256;   // 16x16 per warp (A region free)
#pragma unroll
    for (int tm = 0; tm < 2; ++tm) {
#pragma unroll
        for (int tn = 0; tn < 4; ++tn) {
            wmma::store_matrix_sync(scratch, acc[tm][tn], 16, wmma::mem_row_major);
            __syncwarp();
            const int r = lid >> 1, c0 = (lid & 1) * 8;
            const int lrow = wm * 32 + tm * 16 + r;
            const float inv = 1.0f / (float)degs[lrow];
            const float* s = scratch + r * 16 + c0;
            uint32_t pk[4];
#pragma unroll
            for (int j = 0; j < 4; ++j) {
                __half2 h = __floats2half2_rn(s[2 * j] * inv, s[2 * j + 1] * inv);
                pk[j] = *reinterpret_cast<uint32_t*>(&h);
            }
            *(uint4*)(aggS + (size_t)lrow * BSTR + wn * 64 + tn * 16 + c0) =
                make_uint4(pk[0], pk[1], pk[2], pk[3]);
            __syncwarp();
        }
    }
    __syncthreads();

    // ---- stage 2: out_tile = aggS @ W^T + b  (W streamed from L2) ----
    wmma::fragment<wmma::accumulator, 16, 16, 16, float> acc2[2][4];
#pragma unroll
    for (int tm = 0; tm < 2; ++tm)
#pragma unroll
        for (int tn = 0; tn < 4; ++tn) wmma::fill_fragment(acc2[tm][tn], 0.0f);

#pragma unroll 4
    for (int k16 = 0; k16 < 16; ++k16) {
        wmma::fragment<wmma::matrix_a, 16, 16, 16, half, wmma::row_major> a0, a1;
        wmma::load_matrix_sync(a0, aggS + (wm * 32 + 0) * BSTR + k16 * 16, BSTR);
        wmma::load_matrix_sync(a1, aggS + (wm * 32 + 16) * BSTR + k16 * 16, BSTR);
#pragma unroll
        for (int tn = 0; tn < 4; ++tn) {
            wmma::fragment<wmma::matrix_b, 16, 16, 16, half, wmma::col_major> b;
            wmma::load_matrix_sync(b, g_Wh + (size_t)(wn * 64 + tn * 16) * DF + k16 * 16, DF);
            wmma::mma_sync(acc2[0][tn], a0, b, acc2[0][tn]);
            wmma::mma_sync(acc2[1][tn], a1, b, acc2[1][tn]);
        }
    }

    // ---- epilogue 2: + bias, store f32 coalesced ----
#pragma unroll
    for (int tm = 0; tm < 2; ++tm) {
#pragma unroll
        for (int tn = 0; tn < 4; ++tn) {
            wmma::store_matrix_sync(scratch, acc2[tm][tn], 16, wmma::mem_row_major);
            __syncwarp();
            const int r = lid >> 1, c0 = (lid & 1) * 8;
            const int grow = blk * MT + wm * 32 + tm * 16 + r;
            const int gcol = wn * 64 + tn * 16 + c0;
            const float* s = scratch + r * 16 + c0;
            float4 o0, o1;
            o0.x = s[0] + biasS[gcol + 0];  o0.y = s[1] + biasS[gcol + 1];
            o0.z = s[2] + biasS[gcol + 2];  o0.w = s[3] + biasS[gcol + 3];
            o1.x = s[4] + biasS[gcol + 4];  o1.y = s[5] + biasS[gcol + 5];
            o1.z = s[6] + biasS[gcol + 6];  o1.w = s[7] + biasS[gcol + 7];
            float4* dst = (float4*)(out + (size_t)grow * DF + gcol);
            dst[0] = o0;
            dst[1] = o1;
            __syncwarp();
        }
    }
}

extern "C" void kernel_launch(void* const* d_in, const int* in_sizes, int n_in,
                              void* d_out, int out_size) {
    const float* x    = (const float*)d_in[0];
    const int*   adj  = (const int*)d_in[1];
    const float* W    = (const float*)d_in[2];
    const float* bias = (const float*)d_in[3];
    float* out = (float*)d_out;

    cudaFuncSetAttribute((const void*)k_main,
                         cudaFuncAttributeMaxDynamicSharedMemorySize, SMEM_TOTAL);

    k_prep<<<XBLKS + DF * DF / 256, 256>>>(x, W);
    k_main<<<NN / MT, 512, SMEM_TOTAL>>>(adj, bias, out);
}